// round 4
// baseline (speedup 1.0000x reference)
#include <cuda_runtime.h>
#include <float.h>

// AttentionSelector, fused single kernel (R4: de-serialized phase 1).
//  - Warp per bag, 8 bags per CTA.
//  - Per bag, tiles of <=CAP rows:
//      loop A: logits -> smem (independent iterations, high MLP, low regs)
//      softmax over tile in smem with cross-tile online rescale
//      loop B: att[c] += w_i * repre (no reduces; rows hit L1/L2)
//  - Phase 4: register-tiled 7x8 micro-GEMM, rel read once per CTA.
//
// scope/labels are int32 on device (JAX x64-disabled downgrades int64).

static constexpr int Dd  = 690;   // feature dim
static constexpr int RR  = 53;    // num relations
static constexpr int NT  = 256;   // threads per CTA
static constexpr int NW  = 8;     // warps = bags per CTA
static constexpr int PAD = 704;   // smem att row stride
static constexpr int NC  = 22;    // ceil(690/32) k-chunks per lane
static constexpr int RPW = 7;     // rel rows per warp in phase 4
static constexpr int CAP = 512;   // rows per tile (max bag ~100; tiling = correct anyway)

__global__ __launch_bounds__(NT, 3) void bag_kernel(
    const float* __restrict__ repre,
    const float* __restrict__ rel,
    const float* __restrict__ bias,
    const int*   __restrict__ scope,
    const int*   __restrict__ labels,
    float* __restrict__ out)
{
    __shared__ __align__(16) float s_log[NW][CAP];   // 16 KB: logits -> exp weights
    __shared__ __align__(16) float s_att[NW * PAD];  // 22.5 KB

    const int tid  = threadIdx.x;
    const int lane = tid & 31;
    const int wid  = tid >> 5;
    const int bag  = blockIdx.x * NW + wid;

    const int start = scope[2 * bag];
    const int end   = scope[2 * bag + 1];

    float att[NC];
#pragma unroll
    for (int c = 0; c < NC; c++) att[c] = 0.f;
    float m = -FLT_MAX;
    float s = 0.f;

    for (int t = start; t < end; t += CAP) {
        const int tn = min(CAP, end - t);

        // ---- loop A: logits for tile rows (iterations independent) ----
        for (int i = 0; i < tn; i++) {
            const float* rp = repre + (t + i) * Dd;
            const float* lp = rel + labels[t + i] * Dd;
            float acc = 0.f;
#pragma unroll
            for (int c = 0; c < NC; c++) {
                const int k = c * 32 + lane;
                if (k < Dd) acc = fmaf(rp[k], lp[k], acc);
            }
#pragma unroll
            for (int o = 16; o; o >>= 1) acc += __shfl_xor_sync(0xffffffffu, acc, o);
            if (lane == 0) s_log[wid][i] = acc;
        }
        __syncwarp();

        // ---- tile max ----
        float tm = -FLT_MAX;
        for (int j = lane; j < tn; j += 32) tm = fmaxf(tm, s_log[wid][j]);
#pragma unroll
        for (int o = 16; o; o >>= 1) tm = fmaxf(tm, __shfl_xor_sync(0xffffffffu, tm, o));

        const float M = fmaxf(m, tm);                 // finite after first tile
        const float sc = (m == -FLT_MAX) ? 0.f : __expf(m - M);
        s *= sc;
#pragma unroll
        for (int c = 0; c < NC; c++) att[c] *= sc;
        m = M;

        // ---- exp + partial sum; weights back to smem ----
        float ps = 0.f;
        for (int j = lane; j < tn; j += 32) {
            const float e = __expf(s_log[wid][j] - M);
            s_log[wid][j] = e;
            ps += e;
        }
#pragma unroll
        for (int o = 16; o; o >>= 1) ps += __shfl_xor_sync(0xffffffffu, ps, o);
        s += ps;
        __syncwarp();

        // ---- loop B: weighted accumulate (no reduces; rows re-hit L1/L2) ----
        for (int i = 0; i < tn; i++) {
            const float w = s_log[wid][i];            // smem broadcast
            const float* rp = repre + (t + i) * Dd;
#pragma unroll
            for (int c = 0; c < NC; c++) {
                const int k = c * 32 + lane;
                if (k < Dd) att[c] = fmaf(w, rp[k], att[c]);
            }
        }
        __syncwarp();
    }

    // normalize, stage to smem
    const float inv = 1.0f / s;
#pragma unroll
    for (int c = 0; c < NC; c++) {
        const int k = c * 32 + lane;
        if (k < Dd) s_att[wid * PAD + k] = att[c] * inv;
    }
    __syncthreads();

    // ---- phase 4: out[bag][r] = dot(att[bag], rel[r]) + bias[r]
    //      warp owns RPW rel rows across all NW bags (7x8 register tile) ----
    const int r0 = wid * RPW;
    float acc2[RPW][NW];
#pragma unroll
    for (int j = 0; j < RPW; j++)
#pragma unroll
        for (int b = 0; b < NW; b++) acc2[j][b] = 0.f;

    for (int c = 0; c < NC; c++) {                    // rolled: keep regs low
        const int k = c * 32 + lane;
        const bool v = (k < Dd);
        float a[NW];
#pragma unroll
        for (int b = 0; b < NW; b++) a[b] = v ? s_att[b * PAD + k] : 0.f;
#pragma unroll
        for (int j = 0; j < RPW; j++) {
            const int r = r0 + j;
            const float rv = (v && r < RR) ? rel[r * Dd + k] : 0.f;
#pragma unroll
            for (int b = 0; b < NW; b++)
                acc2[j][b] = fmaf(rv, a[b], acc2[j][b]);
        }
    }

#pragma unroll
    for (int j = 0; j < RPW; j++) {
        const int r = r0 + j;
#pragma unroll
        for (int b = 0; b < NW; b++) {
            float v = acc2[j][b];
#pragma unroll
            for (int o = 16; o; o >>= 1) v += __shfl_xor_sync(0xffffffffu, v, o);
            if (lane == 0 && r < RR)
                out[(blockIdx.x * NW + b) * RR + r] = v + bias[r];
        }
    }
}

extern "C" void kernel_launch(void* const* d_in, const int* in_sizes, int n_in,
                              void* d_out, int out_size) {
    const float* repre  = (const float*)d_in[0];
    const float* rel    = (const float*)d_in[1];
    const float* bias   = (const float*)d_in[2];
    const int*   scope  = (const int*)d_in[3];
    const int*   labels = (const int*)d_in[4];
    float* out = (float*)d_out;

    const int num_bags = in_sizes[3] / 2;   // 25000
    const int grid = num_bags / NW;         // 3125 (exact)
    bag_kernel<<<grid, NT>>>(repre, rel, bias, scope, labels, out);
}

// round 5
// speedup vs baseline: 2.4540x; 2.4540x over previous
#include <cuda_runtime.h>
#include <float.h>

// AttentionSelector (R5): CTA = 8 consecutive bags = one contiguous row span.
//  P1: warps stride over ALL span rows -> logits to smem (row-parallel, no state)
//  P2: warp w does softmax for bag w in smem
//  P3: warp w streams its bag's rows once more (L1-hot) -> att in regs, no reduces
//  P4: register-tiled micro-GEMM (7 rel rows x 8 bags per warp, split 4+3),
//      rel read once per CTA.
// scope/labels are int32 on device (JAX x64-disabled downgrades int64).

static constexpr int Dd  = 690;
static constexpr int F2  = 345;   // float2 per row
static constexpr int NCH = 11;    // ceil(345/32) float2-chunks per lane
static constexpr int RR  = 53;
static constexpr int NT  = 256;
static constexpr int NW  = 8;     // warps = bags per CTA
static constexpr int SP2 = 352;   // s_att2 row stride in float2 (mult of 32)
static constexpr int RPW = 7;     // rel rows per warp in P4 (8*7=56 >= 53)
static constexpr int CAP = 512;   // max rows per CTA span (fallback below)

__device__ __forceinline__ float wsum(float v) {
#pragma unroll
    for (int o = 16; o; o >>= 1) v += __shfl_xor_sync(0xffffffffu, v, o);
    return v;
}
__device__ __forceinline__ float wmax(float v) {
#pragma unroll
    for (int o = 16; o; o >>= 1) v = fmaxf(v, __shfl_xor_sync(0xffffffffu, v, o));
    return v;
}

__global__ __launch_bounds__(NT, 4) void bag_kernel(
    const float* __restrict__ repre,
    const float* __restrict__ rel,
    const float* __restrict__ bias,
    const int*   __restrict__ scope,
    const int*   __restrict__ labels,
    float* __restrict__ out)
{
    __shared__ float  s_log[CAP];            // 2 KB: logits -> weights
    __shared__ __align__(16) float2 s_att2[NW * SP2];  // 22.5 KB

    const int tid  = threadIdx.x;
    const int lane = tid & 31;
    const int wid  = tid >> 5;
    const int bag0 = blockIdx.x * NW;
    const int bag  = bag0 + wid;

    const int start = scope[2 * bag];
    const int end   = scope[2 * bag + 1];
    const int row0  = scope[2 * bag0];             // span start (bags contiguous)
    const int row1  = scope[2 * (bag0 + NW - 1) + 1];  // span end

    if (row1 - row0 <= CAP) {
        // ---- P1: logits for every row in the span, warp-strided ----
        for (int i = row0 + wid; i < row1; i += NW) {
            const float2* rp = reinterpret_cast<const float2*>(repre + i * Dd);
            const float2* lp = reinterpret_cast<const float2*>(rel + labels[i] * Dd);
            float acc = 0.f;
#pragma unroll
            for (int c = 0; c < NCH; c++) {
                const int k = c * 32 + lane;
                if (k < F2) {
                    const float2 x = rp[k], y = lp[k];
                    acc = fmaf(x.x, y.x, acc);
                    acc = fmaf(x.y, y.y, acc);
                }
            }
            acc = wsum(acc);
            if (lane == 0) s_log[i - row0] = acc;
        }
        __syncthreads();

        // ---- P2: softmax for own bag (in smem) ----
        const int n   = end - start;
        const int off = start - row0;
        float tm = -FLT_MAX;
        for (int j = lane; j < n; j += 32) tm = fmaxf(tm, s_log[off + j]);
        tm = wmax(tm);
        float ps = 0.f;
        for (int j = lane; j < n; j += 32) {
            const float e = __expf(s_log[off + j] - tm);
            s_log[off + j] = e;
            ps += e;
        }
        ps = wsum(ps);
        const float inv = 1.0f / ps;
        __syncwarp();

        // ---- P3: weighted pool of own bag's rows (L1-hot, no reduces) ----
        float2 att[NCH];
#pragma unroll
        for (int c = 0; c < NCH; c++) att[c] = make_float2(0.f, 0.f);
        for (int i = 0; i < n; i++) {
            const float w = s_log[off + i];
            const float2* rp = reinterpret_cast<const float2*>(repre + (start + i) * Dd);
#pragma unroll
            for (int c = 0; c < NCH; c++) {
                const int k = c * 32 + lane;
                if (k < F2) {
                    const float2 x = rp[k];
                    att[c].x = fmaf(w, x.x, att[c].x);
                    att[c].y = fmaf(w, x.y, att[c].y);
                }
            }
        }
#pragma unroll
        for (int c = 0; c < NCH; c++) {
            const int k = c * 32 + lane;
            if (k < F2) s_att2[wid * SP2 + k] = make_float2(att[c].x * inv, att[c].y * inv);
        }
    } else {
        // ---- fallback for giant spans (block-uniform branch; correct, slow) ----
        float tm = -FLT_MAX;
        for (int i = start; i < end; i++) {
            const float2* rp = reinterpret_cast<const float2*>(repre + i * Dd);
            const float2* lp = reinterpret_cast<const float2*>(rel + labels[i] * Dd);
            float acc = 0.f;
#pragma unroll
            for (int c = 0; c < NCH; c++) {
                const int k = c * 32 + lane;
                if (k < F2) {
                    const float2 x = rp[k], y = lp[k];
                    acc = fmaf(x.x, y.x, acc);
                    acc = fmaf(x.y, y.y, acc);
                }
            }
            tm = fmaxf(tm, wsum(acc));
        }
        float2 att[NCH];
#pragma unroll
        for (int c = 0; c < NCH; c++) att[c] = make_float2(0.f, 0.f);
        float s = 0.f;
        for (int i = start; i < end; i++) {
            const float2* rp = reinterpret_cast<const float2*>(repre + i * Dd);
            const float2* lp = reinterpret_cast<const float2*>(rel + labels[i] * Dd);
            float acc = 0.f;
            float2 x[NCH];
#pragma unroll
            for (int c = 0; c < NCH; c++) {
                const int k = c * 32 + lane;
                x[c] = make_float2(0.f, 0.f);
                if (k < F2) {
                    x[c] = rp[k];
                    const float2 y = lp[k];
                    acc = fmaf(x[c].x, y.x, acc);
                    acc = fmaf(x[c].y, y.y, acc);
                }
            }
            const float e = __expf(wsum(acc) - tm);
            s += e;
#pragma unroll
            for (int c = 0; c < NCH; c++) {
                att[c].x = fmaf(e, x[c].x, att[c].x);
                att[c].y = fmaf(e, x[c].y, att[c].y);
            }
        }
        const float inv = 1.0f / s;
#pragma unroll
        for (int c = 0; c < NCH; c++) {
            const int k = c * 32 + lane;
            if (k < F2) s_att2[wid * SP2 + k] = make_float2(att[c].x * inv, att[c].y * inv);
        }
    }
    __syncthreads();

    // ---- P4: out[bag][r] = dot(att[bag], rel[r]) + bias[r]
    //      warp owns 7 rel rows; split 4+3 to keep acc regs at 32 ----
    const int r0w = wid * RPW;
#pragma unroll
    for (int g = 0; g < 2; g++) {
        const int jb = g ? 4 : 0;
        const int jn = g ? 3 : 4;
        float acc4[4][NW];
#pragma unroll
        for (int j = 0; j < 4; j++)
#pragma unroll
            for (int b = 0; b < NW; b++) acc4[j][b] = 0.f;

        for (int c = 0; c < NCH; c++) {
            const int k = c * 32 + lane;
            const bool v = (k < F2);
            float2 a[NW];
#pragma unroll
            for (int b = 0; b < NW; b++)
                a[b] = v ? s_att2[b * SP2 + k] : make_float2(0.f, 0.f);
#pragma unroll
            for (int j = 0; j < 4; j++) {
                if (j >= jn) break;
                const int r = r0w + jb + j;
                float2 rv = make_float2(0.f, 0.f);
                if (v && r < RR)
                    rv = reinterpret_cast<const float2*>(rel)[r * F2 + k];
#pragma unroll
                for (int b = 0; b < NW; b++) {
                    acc4[j][b] = fmaf(rv.x, a[b].x, acc4[j][b]);
                    acc4[j][b] = fmaf(rv.y, a[b].y, acc4[j][b]);
                }
            }
        }
#pragma unroll
        for (int j = 0; j < 4; j++) {
            if (j >= jn) break;
            const int r = r0w + jb + j;
#pragma unroll
            for (int b = 0; b < NW; b++) {
                const float v = wsum(acc4[j][b]);
                if (lane == 0 && r < RR)
                    out[(bag0 + b) * RR + r] = v + bias[r];
            }
        }
    }
}

extern "C" void kernel_launch(void* const* d_in, const int* in_sizes, int n_in,
                              void* d_out, int out_size) {
    const float* repre  = (const float*)d_in[0];
    const float* rel    = (const float*)d_in[1];
    const float* bias   = (const float*)d_in[2];
    const int*   scope  = (const int*)d_in[3];
    const int*   labels = (const int*)d_in[4];
    float* out = (float*)d_out;

    const int num_bags = in_sizes[3] / 2;   // 25000
    const int grid = num_bags / NW;         // 3125 (exact)
    bag_kernel<<<grid, NT>>>(repre, rel, bias, scope, labels, out);
}

// round 6
// speedup vs baseline: 2.5040x; 1.0204x over previous
#include <cuda_runtime.h>
#include <float.h>

// AttentionSelector (R6 = R5 + ILP): CTA = 8 consecutive bags = contiguous span.
//  P1: warps stride over span rows, 2 rows/iter, 4 partial accs -> logits to smem
//  P2: warp w softmax for bag w in smem
//  P3: warp w streams its bag rows (2/iter) -> att in regs, no reduces
//  P4: register-tiled micro-GEMM (7 rel rows x 8 bags per warp, split 4+3)
// scope/labels are int32 on device (JAX x64-disabled downgrades int64).

static constexpr int Dd  = 690;
static constexpr int F2  = 345;   // float2 per row
static constexpr int NCH = 11;    // ceil(345/32) float2-chunks per lane
static constexpr int RR  = 53;
static constexpr int NT  = 256;
static constexpr int NW  = 8;     // warps = bags per CTA
static constexpr int SP2 = 352;   // s_att2 row stride in float2
static constexpr int RPW = 7;     // rel rows per warp in P4
static constexpr int CAP = 512;   // max rows per CTA span (fallback below)

__device__ __forceinline__ float wsum(float v) {
#pragma unroll
    for (int o = 16; o; o >>= 1) v += __shfl_xor_sync(0xffffffffu, v, o);
    return v;
}
__device__ __forceinline__ float wmax(float v) {
#pragma unroll
    for (int o = 16; o; o >>= 1) v = fmaxf(v, __shfl_xor_sync(0xffffffffu, v, o));
    return v;
}

// warp-collective dot of row rp with rel row lp, 4 partial accumulators
__device__ __forceinline__ float dot_row(const float2* __restrict__ rp,
                                         const float2* __restrict__ lp,
                                         int lane) {
    float pa0 = 0.f, pa1 = 0.f, pa2 = 0.f, pa3 = 0.f;
#pragma unroll
    for (int c = 0; c < NCH; c++) {
        const int k = c * 32 + lane;
        if (k < F2) {
            const float2 x = rp[k], y = lp[k];
            float* pa = (c & 3) == 0 ? &pa0 : (c & 3) == 1 ? &pa1 : (c & 3) == 2 ? &pa2 : &pa3;
            *pa = fmaf(x.x, y.x, *pa);
            *pa = fmaf(x.y, y.y, *pa);
        }
    }
    return (pa0 + pa1) + (pa2 + pa3);
}

__global__ __launch_bounds__(NT, 4) void bag_kernel(
    const float* __restrict__ repre,
    const float* __restrict__ rel,
    const float* __restrict__ bias,
    const int*   __restrict__ scope,
    const int*   __restrict__ labels,
    float* __restrict__ out)
{
    __shared__ float  s_log[CAP];
    __shared__ __align__(16) float2 s_att2[NW * SP2];  // 22.5 KB

    const int tid  = threadIdx.x;
    const int lane = tid & 31;
    const int wid  = tid >> 5;
    const int bag0 = blockIdx.x * NW;
    const int bag  = bag0 + wid;

    const int start = scope[2 * bag];
    const int end   = scope[2 * bag + 1];
    const int row0  = scope[2 * bag0];
    const int row1  = scope[2 * (bag0 + NW - 1) + 1];

    if (row1 - row0 <= CAP) {
        // ---- P1: logits for span rows, warp-strided, 2 rows per iteration ----
        int i = row0 + wid;
        for (; i + NW < row1; i += 2 * NW) {
            const int i2 = i + NW;
            const float2* rp0 = reinterpret_cast<const float2*>(repre + i  * Dd);
            const float2* lp0 = reinterpret_cast<const float2*>(rel + labels[i]  * Dd);
            const float2* rp1 = reinterpret_cast<const float2*>(repre + i2 * Dd);
            const float2* lp1 = reinterpret_cast<const float2*>(rel + labels[i2] * Dd);
            float a0 = 0.f, a1 = 0.f, b0 = 0.f, b1 = 0.f;
#pragma unroll
            for (int c = 0; c < NCH; c++) {
                const int k = c * 32 + lane;
                if (k < F2) {
                    const float2 x0 = rp0[k], y0 = lp0[k];
                    const float2 x1 = rp1[k], y1 = lp1[k];
                    if (c & 1) {
                        a1 = fmaf(x0.x, y0.x, a1); a1 = fmaf(x0.y, y0.y, a1);
                        b1 = fmaf(x1.x, y1.x, b1); b1 = fmaf(x1.y, y1.y, b1);
                    } else {
                        a0 = fmaf(x0.x, y0.x, a0); a0 = fmaf(x0.y, y0.y, a0);
                        b0 = fmaf(x1.x, y1.x, b0); b0 = fmaf(x1.y, y1.y, b0);
                    }
                }
            }
            float accA = a0 + a1;
            float accB = b0 + b1;
            // interleaved butterfly reduces (independent shuffle chains)
#pragma unroll
            for (int o = 16; o; o >>= 1) {
                accA += __shfl_xor_sync(0xffffffffu, accA, o);
                accB += __shfl_xor_sync(0xffffffffu, accB, o);
            }
            if (lane == 0) { s_log[i - row0] = accA; s_log[i2 - row0] = accB; }
        }
        if (i < row1) {
            const float2* rp = reinterpret_cast<const float2*>(repre + i * Dd);
            const float2* lp = reinterpret_cast<const float2*>(rel + labels[i] * Dd);
            const float acc = wsum(dot_row(rp, lp, lane));
            if (lane == 0) s_log[i - row0] = acc;
        }
        __syncthreads();

        // ---- P2: softmax for own bag ----
        const int n   = end - start;
        const int off = start - row0;
        float tm = -FLT_MAX;
        for (int j = lane; j < n; j += 32) tm = fmaxf(tm, s_log[off + j]);
        tm = wmax(tm);
        float ps = 0.f;
        for (int j = lane; j < n; j += 32) {
            const float e = __expf(s_log[off + j] - tm);
            s_log[off + j] = e;
            ps += e;
        }
        ps = wsum(ps);
        const float inv = 1.0f / ps;
        __syncwarp();

        // ---- P3: weighted pool of own bag (2 rows/iter, no reduces) ----
        float2 att[NCH];
#pragma unroll
        for (int c = 0; c < NCH; c++) att[c] = make_float2(0.f, 0.f);
        int r = 0;
        for (; r + 2 <= n; r += 2) {
            const float w0 = s_log[off + r];
            const float w1 = s_log[off + r + 1];
            const float2* rp0 = reinterpret_cast<const float2*>(repre + (start + r)     * Dd);
            const float2* rp1 = reinterpret_cast<const float2*>(repre + (start + r + 1) * Dd);
#pragma unroll
            for (int c = 0; c < NCH; c++) {
                const int k = c * 32 + lane;
                if (k < F2) {
                    const float2 x0 = rp0[k], x1 = rp1[k];
                    att[c].x = fmaf(w0, x0.x, att[c].x);
                    att[c].y = fmaf(w0, x0.y, att[c].y);
                    att[c].x = fmaf(w1, x1.x, att[c].x);
                    att[c].y = fmaf(w1, x1.y, att[c].y);
                }
            }
        }
        if (r < n) {
            const float w = s_log[off + r];
            const float2* rp = reinterpret_cast<const float2*>(repre + (start + r) * Dd);
#pragma unroll
            for (int c = 0; c < NCH; c++) {
                const int k = c * 32 + lane;
                if (k < F2) {
                    const float2 x = rp[k];
                    att[c].x = fmaf(w, x.x, att[c].x);
                    att[c].y = fmaf(w, x.y, att[c].y);
                }
            }
        }
#pragma unroll
        for (int c = 0; c < NCH; c++) {
            const int k = c * 32 + lane;
            if (k < F2) s_att2[wid * SP2 + k] = make_float2(att[c].x * inv, att[c].y * inv);
        }
    } else {
        // ---- fallback for giant spans (block-uniform branch; correct, slow) ----
        float tm = -FLT_MAX;
        for (int i = start; i < end; i++) {
            const float2* rp = reinterpret_cast<const float2*>(repre + i * Dd);
            const float2* lp = reinterpret_cast<const float2*>(rel + labels[i] * Dd);
            tm = fmaxf(tm, wsum(dot_row(rp, lp, lane)));
        }
        float2 att[NCH];
#pragma unroll
        for (int c = 0; c < NCH; c++) att[c] = make_float2(0.f, 0.f);
        float s = 0.f;
        for (int i = start; i < end; i++) {
            const float2* rp = reinterpret_cast<const float2*>(repre + i * Dd);
            const float2* lp = reinterpret_cast<const float2*>(rel + labels[i] * Dd);
            const float e = __expf(wsum(dot_row(rp, lp, lane)) - tm);
            s += e;
#pragma unroll
            for (int c = 0; c < NCH; c++) {
                const int k = c * 32 + lane;
                if (k < F2) {
                    const float2 x = rp[k];
                    att[c].x = fmaf(e, x.x, att[c].x);
                    att[c].y = fmaf(e, x.y, att[c].y);
                }
            }
        }
        const float inv = 1.0f / s;
#pragma unroll
        for (int c = 0; c < NCH; c++) {
            const int k = c * 32 + lane;
            if (k < F2) s_att2[wid * SP2 + k] = make_float2(att[c].x * inv, att[c].y * inv);
        }
    }
    __syncthreads();

    // ---- P4: out[bag][r] = dot(att[bag], rel[r]) + bias[r] (7x8 tile, 4+3) ----
    const int r0w = wid * RPW;
#pragma unroll
    for (int g = 0; g < 2; g++) {
        const int jb = g ? 4 : 0;
        const int jn = g ? 3 : 4;
        float acc4[4][NW];
#pragma unroll
        for (int j = 0; j < 4; j++)
#pragma unroll
            for (int b = 0; b < NW; b++) acc4[j][b] = 0.f;

        for (int c = 0; c < NCH; c++) {
            const int k = c * 32 + lane;
            const bool v = (k < F2);
            float2 a[NW];
#pragma unroll
            for (int b = 0; b < NW; b++)
                a[b] = v ? s_att2[b * SP2 + k] : make_float2(0.f, 0.f);
#pragma unroll
            for (int j = 0; j < 4; j++) {
                if (j >= jn) break;
                const int rr = r0w + jb + j;
                float2 rv = make_float2(0.f, 0.f);
                if (v && rr < RR)
                    rv = reinterpret_cast<const float2*>(rel)[rr * F2 + k];
#pragma unroll
                for (int b = 0; b < NW; b++) {
                    acc4[j][b] = fmaf(rv.x, a[b].x, acc4[j][b]);
                    acc4[j][b] = fmaf(rv.y, a[b].y, acc4[j][b]);
                }
            }
        }
#pragma unroll
        for (int j = 0; j < 4; j++) {
            if (j >= jn) break;
            const int rr = r0w + jb + j;
#pragma unroll
            for (int b = 0; b < NW; b++) {
                const float v = wsum(acc4[j][b]);
                if (lane == 0 && rr < RR)
                    out[(bag0 + b) * RR + rr] = v + bias[rr];
            }
        }
    }
}

extern "C" void kernel_launch(void* const* d_in, const int* in_sizes, int n_in,
                              void* d_out, int out_size) {
    const float* repre  = (const float*)d_in[0];
    const float* rel    = (const float*)d_in[1];
    const float* bias   = (const float*)d_in[2];
    const int*   scope  = (const int*)d_in[3];
    const int*   labels = (const int*)d_in[4];
    float* out = (float*)d_out;

    const int num_bags = in_sizes[3] / 2;   // 25000
    const int grid = num_bags / NW;         // 3125 (exact)
    bag_kernel<<<grid, NT>>>(repre, rel, bias, scope, labels, out);
}